// round 5
// baseline (speedup 1.0000x reference)
#include <cuda_runtime.h>
#include <cstdint>

#define DD 128
#define NMAX 50176
#define EMAX 800256

// ---------------- scratch (__device__ globals; no allocation) ----------------
__device__ float g_ht[(size_t)NMAX * DD];   // GEMM output (post leaky_relu)
__device__ float g_h2[(size_t)NMAX * DD];   // agg output (next GEMM input)
__device__ float g_sl[NMAX], g_sr[NMAX];
__device__ float g_ew[EMAX];
__device__ int   g_deg[NMAX];
__device__ int   g_off[NMAX + 1];
__device__ int   g_pos[NMAX];
__device__ int   g_col[EMAX];

// ---------------- packed f32x2 helpers (Blackwell base ISA) ----------------
#define FMAX2(acc, a, b) \
    asm("fma.rn.f32x2 %0, %1, %2, %0;" : "+l"(acc) : "l"(a), "l"(b))
#define PACKX2(d, x) \
    asm("mov.b64 %0, {%1, %1};" : "=l"(d) : "f"(x))
#define UNPACKX2(lo, hi, v) \
    asm("mov.b64 {%0, %1}, %2;" : "=f"(lo), "=f"(hi) : "l"(v))

// ---------------- CSR build ----------------
__global__ void k_zero(int N) {
    int i = blockIdx.x * blockDim.x + threadIdx.x;
    if (i < N) g_deg[i] = 0;
}
__global__ void k_count(const int* __restrict__ src, int E) {
    int e = blockIdx.x * blockDim.x + threadIdx.x;
    if (e < E) atomicAdd(&g_deg[src[e]], 1);
}
__global__ __launch_bounds__(1024) void k_scan(int N, int E) {
    __shared__ int sh[1024];
    int tid = threadIdx.x;
    int per = (N + 1023) >> 10;
    int s = tid * per;
    int e = s + per; if (e > N) e = N;
    int sum = 0;
    for (int i = s; i < e; i++) sum += g_deg[i];
    sh[tid] = sum;
    __syncthreads();
    for (int o = 1; o < 1024; o <<= 1) {
        int t = (tid >= o) ? sh[tid - o] : 0;
        __syncthreads();
        sh[tid] += t;
        __syncthreads();
    }
    int run = sh[tid] - sum;
    for (int i = s; i < e; i++) { g_off[i] = run; g_pos[i] = run; run += g_deg[i]; }
    if (tid == 1023) g_off[N] = E;
}
__global__ void k_scatter(const int* __restrict__ src, const int* __restrict__ dst, int E) {
    int e = blockIdx.x * blockDim.x + threadIdx.x;
    if (e < E) {
        int p = atomicAdd(&g_pos[src[e]], 1);
        g_col[p] = dst[e];
    }
}

// ---------------- fp32 GEMM with packed FFMA2 ----------------
// CTA: 64 rows x 128 cols. Warp: 8 rows x 128 cols (lane: 4 cols as 2 f32x2).
// ht = leaky_relu(in @ W + b); fused s_left/s_right dots.
__global__ __launch_bounds__(256) void k_gemm(
    const float* __restrict__ xext, int in_ext,
    const float* __restrict__ W, const float* __restrict__ bias,
    const float* __restrict__ aw, int M)
{
    const float* in = in_ext ? xext : g_h2;
    __shared__ float ws[64 * 128];   // 32 KB  W chunk [64k x 128n]
    __shared__ float hs[64 * 64];    // 16 KB  h tile  [64rows x 64k]

    int tid = threadIdx.x, warp = tid >> 5, lane = tid & 31;
    int r0 = blockIdx.x * 64;
    int c4 = lane * 4;

    unsigned long long acc[8][2];
#pragma unroll
    for (int r = 0; r < 8; r++) { acc[r][0] = 0ULL; acc[r][1] = 0ULL; }

    for (int kc = 0; kc < DD; kc += 64) {
        const float4* wsrc = (const float4*)(W + (size_t)kc * DD);
        float4* wdst = (float4*)ws;
#pragma unroll
        for (int i = 0; i < 8; i++) wdst[tid + i * 256] = wsrc[tid + i * 256];
#pragma unroll
        for (int i = 0; i < 4; i++) {
            int idx = tid + i * 256;          // float4 index 0..1023
            int row = idx >> 4;
            int c = idx & 15;
            float4 v = make_float4(0.f, 0.f, 0.f, 0.f);
            if (r0 + row < M)
                v = *(const float4*)(in + (size_t)(r0 + row) * DD + kc + c * 4);
            *(float4*)(hs + row * 64 + c * 4) = v;
        }
        __syncthreads();

        int wr = warp * 8;
#pragma unroll 4
        for (int k = 0; k < 64; k++) {
            ulonglong2 w2 = *(const ulonglong2*)(ws + k * DD + c4);
#pragma unroll
            for (int r = 0; r < 8; r++) {
                float a = hs[(wr + r) * 64 + k];
                unsigned long long aa;
                PACKX2(aa, a);
                FMAX2(acc[r][0], aa, w2.x);
                FMAX2(acc[r][1], aa, w2.y);
            }
        }
        __syncthreads();
    }

    float4 bb = *(const float4*)(bias + c4);
    float4 al = *(const float4*)(aw + c4);
    float4 ar = *(const float4*)(aw + DD + c4);

#pragma unroll
    for (int r = 0; r < 8; r++) {
        int row = r0 + warp * 8 + r;
        if (row < M) {
            float4 v;
            UNPACKX2(v.x, v.y, acc[r][0]);
            UNPACKX2(v.z, v.w, acc[r][1]);
            v.x += bb.x; v.x = v.x > 0.f ? v.x : 0.2f * v.x;
            v.y += bb.y; v.y = v.y > 0.f ? v.y : 0.2f * v.y;
            v.z += bb.z; v.z = v.z > 0.f ? v.z : 0.2f * v.z;
            v.w += bb.w; v.w = v.w > 0.f ? v.w : 0.2f * v.w;
            *(float4*)(g_ht + (size_t)row * DD + c4) = v;
            float dl = v.x * al.x + v.y * al.y + v.z * al.z + v.w * al.w;
            float dr = v.x * ar.x + v.y * ar.y + v.z * ar.z + v.w * ar.w;
#pragma unroll
            for (int o = 16; o; o >>= 1) {
                dl += __shfl_xor_sync(0xffffffffu, dl, o);
                dr += __shfl_xor_sync(0xffffffffu, dr, o);
            }
            if (lane == 0) { g_sl[row] = dl; g_sr[row] = dr; }
        }
    }
}

// ---------------- per-node softmax + aggregation (warp per node) --------------
// Pass 1: lane-parallel online softmax stats (e cached in regs if deg<=32,
// else spilled to g_ew). Pass 2: lane-parallel weights, then per-edge
// shfl + coalesced 512B row read + FMA (L2-roofline bound).
__global__ __launch_bounds__(256) void k_agg(
    float* __restrict__ extout, int last, const float* __restrict__ abp, int N)
{
    const float* ht = g_ht;
    int gw = (blockIdx.x * blockDim.x + threadIdx.x) >> 5;
    int lane = threadIdx.x & 31;
    if (gw >= N) return;

    int base = g_off[gw], end = g_off[gw + 1];
    int deg = end - base;
    int c4 = lane * 4;
    float4 acc = make_float4(0.f, 0.f, 0.f, 0.f);

    if (deg > 0) {
        float ab = *abp;
        float sli = g_sl[gw];
        float m = -1e30f, s = 0.f;
        float e_reg = 0.f;
        int d_reg = 0;
        bool small = (deg <= 32);

        if (small) {
            if (lane < deg) {
                d_reg = g_col[base + lane];
                e_reg = sli + g_sr[d_reg] + ab;
                m = e_reg; s = 1.f;
            }
        } else {
            for (int k = base + lane; k < end; k += 32) {
                int d = g_col[k];
                float e = sli + g_sr[d] + ab;
                g_ew[k] = e;
                if (e > m) { s = s * __expf(m - e) + 1.f; m = e; }
                else        { s += __expf(e - m); }
            }
        }
#pragma unroll
        for (int o = 16; o; o >>= 1) {
            float mo = __shfl_xor_sync(0xffffffffu, m, o);
            float so = __shfl_xor_sync(0xffffffffu, s, o);
            float mn = fmaxf(m, mo);
            s = s * __expf(m - mn) + so * __expf(mo - mn);
            m = mn;
        }
        float inv = 1.f / s;

        if (small) {
            float w = (lane < deg) ? __expf(e_reg - m) * inv : 0.f;
            for (int j = 0; j < deg; j++) {
                float wj = __shfl_sync(0xffffffffu, w, j);
                int dj = __shfl_sync(0xffffffffu, d_reg, j);
                float4 hv = *(const float4*)(ht + (size_t)dj * DD + c4);
                acc.x += wj * hv.x; acc.y += wj * hv.y;
                acc.z += wj * hv.z; acc.w += wj * hv.w;
            }
        } else {
            for (int k0 = base; k0 < end; k0 += 32) {
                int kk = k0 + lane;
                float w = 0.f; int d = 0;
                if (kk < end) {
                    w = __expf(g_ew[kk] - m) * inv;
                    d = g_col[kk];
                }
                int nd = end - k0; if (nd > 32) nd = 32;
                for (int j = 0; j < nd; j++) {
                    float wj = __shfl_sync(0xffffffffu, w, j);
                    int dj = __shfl_sync(0xffffffffu, d, j);
                    float4 hv = *(const float4*)(ht + (size_t)dj * DD + c4);
                    acc.x += wj * hv.x; acc.y += wj * hv.y;
                    acc.z += wj * hv.z; acc.w += wj * hv.w;
                }
            }
        }
    }
    acc.x = fmaxf(acc.x, 0.f);
    acc.y = fmaxf(acc.y, 0.f);
    acc.z = fmaxf(acc.z, 0.f);
    acc.w = fmaxf(acc.w, 0.f);

    float* out = last ? extout : g_h2;
    *(float4*)(out + (size_t)gw * DD + c4) = acc;
}

// ---------------- launch ----------------
extern "C" void kernel_launch(void* const* d_in, const int* in_sizes, int n_in,
                              void* d_out, int out_size)
{
    const float* x      = (const float*)d_in[0];
    const int*   esrc   = (const int*)d_in[1];
    const int*   edst   = (const int*)d_in[2];
    const float* lin_w  = (const float*)d_in[3];
    const float* lin_b  = (const float*)d_in[4];
    const float* attn_w = (const float*)d_in[5];
    const float* attn_b = (const float*)d_in[6];

    int N = in_sizes[0] / DD;
    int E = in_sizes[1];

    k_zero<<<(N + 255) / 256, 256>>>(N);
    k_count<<<(E + 255) / 256, 256>>>(esrc, E);
    k_scan<<<1, 1024>>>(N, E);
    k_scatter<<<(E + 255) / 256, 256>>>(esrc, edst, E);

    int gB = (N + 63) / 64;
    int aB = (N + 7) / 8;
    for (int l = 0; l < 3; l++) {
        k_gemm<<<gB, 256>>>(x, l == 0 ? 1 : 0,
                            lin_w + (size_t)l * DD * DD,
                            lin_b + (size_t)l * DD,
                            attn_w + (size_t)l * 2 * DD, N);
        k_agg<<<aB, 256>>>((float*)d_out, l == 2 ? 1 : 0, attn_b + l, N);
    }
}

// round 10
// speedup vs baseline: 1.0172x; 1.0172x over previous
#include <cuda_runtime.h>
#include <cstdint>

#define DD 128
#define NMAX 50176
#define EMAX 800256

// ---------------- scratch (__device__ globals; no allocation) ----------------
__device__ float g_h[2][(size_t)NMAX * DD];     // double-buffered post-linear h
__device__ float g_slb[2][NMAX], g_srb[2][NMAX];
__device__ int   g_deg[NMAX];
__device__ int   g_off[NMAX + 1];
__device__ int   g_pos[NMAX];
__device__ int   g_col[EMAX];

// ---------------- CSR build ----------------
__global__ void k_zero(int N) {
    int i = blockIdx.x * blockDim.x + threadIdx.x;
    if (i < N) g_deg[i] = 0;
}
__global__ void k_count(const int* __restrict__ src, int E) {
    int e = blockIdx.x * blockDim.x + threadIdx.x;
    if (e < E) atomicAdd(&g_deg[src[e]], 1);
}
__global__ __launch_bounds__(1024) void k_scan(int N, int E) {
    __shared__ int sh[1024];
    int tid = threadIdx.x;
    int per = (N + 1023) >> 10;
    int s = tid * per;
    int e = s + per; if (e > N) e = N;
    int sum = 0;
    for (int i = s; i < e; i++) sum += g_deg[i];
    sh[tid] = sum;
    __syncthreads();
    for (int o = 1; o < 1024; o <<= 1) {
        int t = (tid >= o) ? sh[tid - o] : 0;
        __syncthreads();
        sh[tid] += t;
        __syncthreads();
    }
    int run = sh[tid] - sum;
    for (int i = s; i < e; i++) { g_off[i] = run; g_pos[i] = run; run += g_deg[i]; }
    if (tid == 1023) g_off[N] = E;
}
__global__ void k_scatter(const int* __restrict__ src, const int* __restrict__ dst, int E) {
    int e = blockIdx.x * blockDim.x + threadIdx.x;
    if (e < E) {
        int p = atomicAdd(&g_pos[src[e]], 1);
        g_col[p] = dst[e];
    }
}

// ---------------- layer-0 GEMM (R1 kernel, parameterized buffers) -------------
__global__ __launch_bounds__(256) void k_gemm0(
    const float* __restrict__ in,
    const float* __restrict__ W, const float* __restrict__ bias,
    const float* __restrict__ aw,
    float* __restrict__ htout, float* __restrict__ slout, float* __restrict__ srout,
    int M)
{
    __shared__ float ws[64 * 128];
    __shared__ float hs[64 * 64];

    int tid = threadIdx.x, warp = tid >> 5, lane = tid & 31;
    int r0 = blockIdx.x * 64;
    int c4 = lane * 4;

    float4 acc[8];
#pragma unroll
    for (int r = 0; r < 8; r++) acc[r] = make_float4(0.f, 0.f, 0.f, 0.f);

    for (int kc = 0; kc < DD; kc += 64) {
        const float4* wsrc = (const float4*)(W + (size_t)kc * DD);
        float4* wdst = (float4*)ws;
#pragma unroll
        for (int i = 0; i < 8; i++) wdst[tid + i * 256] = wsrc[tid + i * 256];
#pragma unroll
        for (int i = 0; i < 4; i++) {
            int idx = tid + i * 256;
            int row = idx >> 4;
            int c = idx & 15;
            float4 v = make_float4(0.f, 0.f, 0.f, 0.f);
            if (r0 + row < M)
                v = *(const float4*)(in + (size_t)(r0 + row) * DD + kc + c * 4);
            *(float4*)(hs + row * 64 + c * 4) = v;
        }
        __syncthreads();
        int wr = warp * 8;
#pragma unroll 8
        for (int k = 0; k < 64; k++) {
            float4 w4 = *(const float4*)(ws + k * DD + c4);
#pragma unroll
            for (int r = 0; r < 8; r++) {
                float a = hs[(wr + r) * 64 + k];
                acc[r].x += a * w4.x; acc[r].y += a * w4.y;
                acc[r].z += a * w4.z; acc[r].w += a * w4.w;
            }
        }
        __syncthreads();
    }

    float4 bb = *(const float4*)(bias + c4);
    float4 al = *(const float4*)(aw + c4);
    float4 ar = *(const float4*)(aw + DD + c4);
#pragma unroll
    for (int r = 0; r < 8; r++) {
        int row = r0 + warp * 8 + r;
        if (row < M) {
            float4 v = acc[r];
            v.x += bb.x; v.x = v.x > 0.f ? v.x : 0.2f * v.x;
            v.y += bb.y; v.y = v.y > 0.f ? v.y : 0.2f * v.y;
            v.z += bb.z; v.z = v.z > 0.f ? v.z : 0.2f * v.z;
            v.w += bb.w; v.w = v.w > 0.f ? v.w : 0.2f * v.w;
            *(float4*)(htout + (size_t)row * DD + c4) = v;
            float dl = v.x * al.x + v.y * al.y + v.z * al.z + v.w * al.w;
            float dr = v.x * ar.x + v.y * ar.y + v.z * ar.z + v.w * ar.w;
#pragma unroll
            for (int o = 16; o; o >>= 1) {
                dl += __shfl_xor_sync(0xffffffffu, dl, o);
                dr += __shfl_xor_sync(0xffffffffu, dr, o);
            }
            if (lane == 0) { slout[row] = dl; srout[row] = dr; }
        }
    }
}

// ---------------- fused agg(l) + gemm(l+1) ------------------------------------
// CTA owns 64 node rows. Phase A: warp-per-node softmax+aggregate into smem.
// Phase B: GEMM those 64 rows straight from smem. Double-buffered ht/sl/sr.
__global__ __launch_bounds__(256) void k_fused(
    const float* __restrict__ htin, const float* __restrict__ slin,
    const float* __restrict__ srin, const float* __restrict__ abp,
    const float* __restrict__ W, const float* __restrict__ bias,
    const float* __restrict__ aw,
    float* __restrict__ htout, float* __restrict__ slout, float* __restrict__ srout,
    int M)
{
    extern __shared__ float sm[];          // [0:8192) h2 tile, [8192:16384) W chunk
    float* h2s = sm;
    float* ws = sm + 8192;

    int tid = threadIdx.x, warp = tid >> 5, lane = tid & 31;
    int r0 = blockIdx.x * 64;
    int c4 = lane * 4;
    float ab = *abp;

    // ---- Phase A: aggregation for rows r0..r0+63 ----
#pragma unroll 1
    for (int i = 0; i < 8; i++) {
        int lrow = warp * 8 + i;
        int gw = r0 + lrow;
        float4 acc = make_float4(0.f, 0.f, 0.f, 0.f);
        if (gw < M) {
            int base = g_off[gw], end = g_off[gw + 1];
            if (end > base) {
                float sli = slin[gw];
                float m = -1e30f, s = 0.f;
                for (int k = base + lane; k < end; k += 32) {
                    int d = g_col[k];
                    float e = sli + srin[d] + ab;
                    if (e > m) { s = s * __expf(m - e) + 1.f; m = e; }
                    else        { s += __expf(e - m); }
                }
#pragma unroll
                for (int o = 16; o; o >>= 1) {
                    float mo = __shfl_xor_sync(0xffffffffu, m, o);
                    float so = __shfl_xor_sync(0xffffffffu, s, o);
                    float mn = fmaxf(m, mo);
                    s = s * __expf(m - mn) + so * __expf(mo - mn);
                    m = mn;
                }
                float inv = 1.f / s;
                float csh = sli + ab - m;
                for (int k = base; k < end; k++) {
                    int d = g_col[k];
                    float w = __expf(csh + srin[d]) * inv;
                    float4 hv = *(const float4*)(htin + (size_t)d * DD + c4);
                    acc.x += w * hv.x; acc.y += w * hv.y;
                    acc.z += w * hv.z; acc.w += w * hv.w;
                }
            }
        }
        acc.x = fmaxf(acc.x, 0.f);
        acc.y = fmaxf(acc.y, 0.f);
        acc.z = fmaxf(acc.z, 0.f);
        acc.w = fmaxf(acc.w, 0.f);
        *(float4*)(h2s + (size_t)lrow * DD + c4) = acc;
    }
    __syncthreads();

    // ---- Phase B: GEMM rows r0..r0+63 from smem ----
    float4 acc[8];
#pragma unroll
    for (int r = 0; r < 8; r++) acc[r] = make_float4(0.f, 0.f, 0.f, 0.f);

    for (int kc = 0; kc < DD; kc += 64) {
        const float4* wsrc = (const float4*)(W + (size_t)kc * DD);
        float4* wdst = (float4*)ws;
#pragma unroll
        for (int i = 0; i < 8; i++) wdst[tid + i * 256] = wsrc[tid + i * 256];
        __syncthreads();
        int wr = warp * 8;
#pragma unroll 8
        for (int k = 0; k < 64; k++) {
            float4 w4 = *(const float4*)(ws + k * DD + c4);
#pragma unroll
            for (int r = 0; r < 8; r++) {
                float a = h2s[(wr + r) * DD + kc + k];
                acc[r].x += a * w4.x; acc[r].y += a * w4.y;
                acc[r].z += a * w4.z; acc[r].w += a * w4.w;
            }
        }
        __syncthreads();
    }

    float4 bb = *(const float4*)(bias + c4);
    float4 al = *(const float4*)(aw + c4);
    float4 ar = *(const float4*)(aw + DD + c4);
#pragma unroll
    for (int r = 0; r < 8; r++) {
        int row = r0 + warp * 8 + r;
        if (row < M) {
            float4 v = acc[r];
            v.x += bb.x; v.x = v.x > 0.f ? v.x : 0.2f * v.x;
            v.y += bb.y; v.y = v.y > 0.f ? v.y : 0.2f * v.y;
            v.z += bb.z; v.z = v.z > 0.f ? v.z : 0.2f * v.z;
            v.w += bb.w; v.w = v.w > 0.f ? v.w : 0.2f * v.w;
            *(float4*)(htout + (size_t)row * DD + c4) = v;
            float dl = v.x * al.x + v.y * al.y + v.z * al.z + v.w * al.w;
            float dr = v.x * ar.x + v.y * ar.y + v.z * ar.z + v.w * ar.w;
#pragma unroll
            for (int o = 16; o; o >>= 1) {
                dl += __shfl_xor_sync(0xffffffffu, dl, o);
                dr += __shfl_xor_sync(0xffffffffu, dr, o);
            }
            if (lane == 0) { slout[row] = dl; srout[row] = dr; }
        }
    }
}

// ---------------- final aggregation -> d_out ----------------------------------
__global__ __launch_bounds__(256) void k_agg_last(
    const float* __restrict__ htin, const float* __restrict__ slin,
    const float* __restrict__ srin, const float* __restrict__ abp,
    float* __restrict__ out, int N)
{
    int gw = (blockIdx.x * blockDim.x + threadIdx.x) >> 5;
    int lane = threadIdx.x & 31;
    if (gw >= N) return;

    int base = g_off[gw], end = g_off[gw + 1];
    int c4 = lane * 4;
    float4 acc = make_float4(0.f, 0.f, 0.f, 0.f);

    if (end > base) {
        float ab = *abp;
        float sli = slin[gw];
        float m = -1e30f, s = 0.f;
        for (int k = base + lane; k < end; k += 32) {
            int d = g_col[k];
            float e = sli + srin[d] + ab;
            if (e > m) { s = s * __expf(m - e) + 1.f; m = e; }
            else        { s += __expf(e - m); }
        }
#pragma unroll
        for (int o = 16; o; o >>= 1) {
            float mo = __shfl_xor_sync(0xffffffffu, m, o);
            float so = __shfl_xor_sync(0xffffffffu, s, o);
            float mn = fmaxf(m, mo);
            s = s * __expf(m - mn) + so * __expf(mo - mn);
            m = mn;
        }
        float inv = 1.f / s;
        float csh = sli + ab - m;
        for (int k = base; k < end; k++) {
            int d = g_col[k];
            float w = __expf(csh + srin[d]) * inv;
            float4 hv = *(const float4*)(htin + (size_t)d * DD + c4);
            acc.x += w * hv.x; acc.y += w * hv.y;
            acc.z += w * hv.z; acc.w += w * hv.w;
        }
    }
    acc.x = fmaxf(acc.x, 0.f);
    acc.y = fmaxf(acc.y, 0.f);
    acc.z = fmaxf(acc.z, 0.f);
    acc.w = fmaxf(acc.w, 0.f);
    *(float4*)(out + (size_t)gw * DD + c4) = acc;
}

// ---------------- launch ----------------
extern "C" void kernel_launch(void* const* d_in, const int* in_sizes, int n_in,
                              void* d_out, int out_size)
{
    const float* x      = (const float*)d_in[0];
    const int*   esrc   = (const int*)d_in[1];
    const int*   edst   = (const int*)d_in[2];
    const float* lin_w  = (const float*)d_in[3];
    const float* lin_b  = (const float*)d_in[4];
    const float* attn_w = (const float*)d_in[5];
    const float* attn_b = (const float*)d_in[6];

    int N = in_sizes[0] / DD;
    int E = in_sizes[1];

    static cudaStream_t s2 = nullptr;
    static cudaEvent_t evA = nullptr, evB = nullptr;
    if (!s2) {
        cudaStreamCreate(&s2);
        cudaEventCreateWithFlags(&evA, cudaEventDisableTiming);
        cudaEventCreateWithFlags(&evB, cudaEventDisableTiming);
        cudaFuncSetAttribute(k_fused, cudaFuncAttributeMaxDynamicSharedMemorySize, 65536);
    }

    float* h0 = nullptr; float* h1 = nullptr;
    float *sl0, *sl1, *sr0, *sr1;
    cudaGetSymbolAddress((void**)&h0, g_h);
    h1 = h0 + (size_t)NMAX * DD;
    cudaGetSymbolAddress((void**)&sl0, g_slb);  sl1 = sl0 + NMAX;
    cudaGetSymbolAddress((void**)&sr0, g_srb);  sr1 = sr0 + NMAX;

    int gB = (N + 63) / 64;
    int aB = (N + 7) / 8;

    // fork: CSR build on s2, concurrent with layer-0 GEMM on main stream
    cudaEventRecord(evA, 0);
    cudaStreamWaitEvent(s2, evA, 0);
    k_zero<<<(N + 255) / 256, 256, 0, s2>>>(N);
    k_count<<<(E + 255) / 256, 256, 0, s2>>>(esrc, E);
    k_scan<<<1, 1024, 0, s2>>>(N, E);
    k_scatter<<<(E + 255) / 256, 256, 0, s2>>>(esrc, edst, E);
    cudaEventRecord(evB, s2);

    k_gemm0<<<gB, 256>>>(x, lin_w, lin_b, attn_w, h0, sl0, sr0, N);

    cudaStreamWaitEvent(0, evB, 0);    // join: agg needs CSR

    // fused agg(0)+gemm(1): read buf0 -> write buf1
    k_fused<<<gB, 256, 65536>>>(h0, sl0, sr0, attn_b + 0,
                                lin_w + (size_t)1 * DD * DD, lin_b + DD,
                                attn_w + (size_t)1 * 2 * DD,
                                h1, sl1, sr1, N);
    // fused agg(1)+gemm(2): read buf1 -> write buf0
    k_fused<<<gB, 256, 65536>>>(h1, sl1, sr1, attn_b + 1,
                                lin_w + (size_t)2 * DD * DD, lin_b + 2 * DD,
                                attn_w + (size_t)2 * 2 * DD,
                                h0, sl0, sr0, N);
    // final agg(2) -> d_out
    k_agg_last<<<aB, 256>>>(h0, sl0, sr0, attn_b + 2, (float*)d_out, N);
}